// round 9
// baseline (speedup 1.0000x reference)
#include <cuda_runtime.h>
#include <cuda_fp16.h>
#include <cstdint>
#include <cstddef>

#define B_ 64
#define S_ 2048
#define H_ 512

// ---------------- scratch (no allocations allowed) ----------------
__device__ float g_q[B_ * H_];            // query projection [B,H]
__device__ float g_ep[2][B_ * S_];        // energy partials per n-half
__device__ float g_energy[B_ * S_];       // exp(energy) weights (0 when masked)
__device__ float g_invden[B_];
__device__ __half g_w1tF[H_ * H_];        // W1^T fp16 [n][k]
__device__ __half g_encF[(size_t)B_ * S_ * H_];  // enc fp16

// ---------------- helpers ----------------
__device__ __forceinline__ uint32_t smem_u32(const void* p) {
    uint32_t a;
    asm("{ .reg .u64 t; cvta.to.shared.u64 t, %1; cvt.u32.u64 %0, t; }" : "=r"(a) : "l"(p));
    return a;
}
#define SW128(o) ((o) ^ (((o) >> 3) & 0x70))

__device__ __forceinline__ uint32_t cvtf2(float lo, float hi) {  // f16x2 {hi,lo}
    uint32_t r;
    asm("cvt.rn.f16x2.f32 %0, %1, %2;" : "=r"(r) : "f"(hi), "f"(lo));
    return r;
}
__device__ __forceinline__ float tanh_fast(float x) {
    float e = __expf(2.0f * x);
    return 1.0f - __fdividef(2.0f, e + 1.0f);
}
__device__ __forceinline__ void cp16(uint32_t dst, const void* src) {
    asm volatile("cp.async.cg.shared.global [%0], [%1], 16;" :: "r"(dst), "l"(src) : "memory");
}
__device__ __forceinline__ void cp_commit() {
    asm volatile("cp.async.commit_group;" ::: "memory");
}
__device__ __forceinline__ void cp_wait2() {
    asm volatile("cp.async.wait_group 2;" ::: "memory");
}
__device__ __forceinline__ void cp_wait1() {
    asm volatile("cp.async.wait_group 1;" ::: "memory");
}
__device__ __forceinline__ void cp_wait0() {
    asm volatile("cp.async.wait_group 0;" ::: "memory");
}
__device__ __forceinline__ void ldmx4(uint32_t* r, uint32_t addr) {
    asm volatile("ldmatrix.sync.aligned.m8n8.x4.shared.b16 {%0,%1,%2,%3}, [%4];"
                 : "=r"(r[0]), "=r"(r[1]), "=r"(r[2]), "=r"(r[3]) : "r"(addr));
}
__device__ __forceinline__ void mma16816(float* d, const uint32_t* a, uint32_t b0, uint32_t b1) {
    asm volatile(
        "mma.sync.aligned.m16n8k16.row.col.f32.f16.f16.f32 "
        "{%0,%1,%2,%3}, {%4,%5,%6,%7}, {%8,%9}, {%0,%1,%2,%3};"
        : "+f"(d[0]), "+f"(d[1]), "+f"(d[2]), "+f"(d[3])
        : "r"(a[0]), "r"(a[1]), "r"(a[2]), "r"(a[3]), "r"(b0), "r"(b1));
}

// ---------------- K0: fused prep (encconv | w1conv | qproj) ----------------
__global__ __launch_bounds__(256) void prep_kernel(const float* __restrict__ enc,
                                                   const int* __restrict__ lens,
                                                   const float* __restrict__ W1,
                                                   const float* __restrict__ dec,
                                                   const float* __restrict__ W2) {
    const int blk = blockIdx.x;
    const int tid = threadIdx.x;

    if (blk < 8192) {                       // ---- encconv (16 rows each) ----
        const int b    = blk >> 7;
        const int row0 = (blk & 127) << 4;
        const int lim  = ((lens[b] + 127) >> 7) << 7;
        if (row0 >= lim) return;
        const size_t base = ((size_t)b * S_ + row0) * H_;
        const float4* src = (const float4*)(enc + base);
        uint2* dh = (uint2*)(g_encF + base);
#pragma unroll 4
        for (int i = tid; i < 2048; i += 256) {
            float4 v = src[i];
            dh[i] = make_uint2(cvtf2(v.x, v.y), cvtf2(v.z, v.w));
        }
    } else if (blk < 9216) {                // ---- w1conv ----
        int idx = (blk - 8192) * 256 + tid; // idx = n*512 + k
        int n = idx >> 9, k = idx & 511;
        g_w1tF[idx] = __float2half(W1[(size_t)k * H_ + n]);
    } else {                                // ---- qproj ----
        const int b = blk - 9216;
        __shared__ float xs[H_];
        xs[tid] = dec[b * H_ + tid];
        xs[tid + 256] = dec[b * H_ + tid + 256];
        __syncthreads();
        float a0 = 0.f, a1 = 0.f;
#pragma unroll 8
        for (int h = 0; h < H_; ++h) {
            float x = xs[h];
            a0 += x * W2[(size_t)h * H_ + tid];
            a1 += x * W2[(size_t)h * H_ + tid + 256];
        }
        g_q[b * H_ + tid] = a0;
        g_q[b * H_ + tid + 256] = a1;
    }
}

// ---------------- K1: fp16 mma.sync energy GEMM ----------------
// CTA: 128 rows x 256 cols, K=512 in 8 chunks of 64, 4-stage cp.async pipeline.
// 16 warps, warp grid 4M x 4N, warp tile 32x64. 1 CTA/SM (193KB smem).
#define STG    49152       // per-stage: A 16KB + B 32KB
#define OFF_B  16384
#define DSMEM  (1024 + 4 * STG)   // 197632

__global__ __launch_bounds__(512, 1) void energy_kernel(const float* __restrict__ Vv,
                                                        const int* __restrict__ lens) {
    // grid: b*32 + tile*2 + nc
    const int nc   = blockIdx.x & 1;
    const int tile = (blockIdx.x >> 1) & 15;
    const int b    = blockIdx.x >> 5;
    const int row0 = tile << 7;
    const int n0   = nc << 8;
    if (row0 >= lens[b]) return;

    extern __shared__ char dsm[];
    __shared__ float qs[256], Vs[256], es4[4][128];

    const int tid  = threadIdx.x;
    const int wid  = tid >> 5;
    const int lane = tid & 31;
    const int mbase = (wid & 3) << 5;   // 0..96
    const int nidx  = wid >> 2;         // 0..3
    const int nbase = nidx << 6;        // 0..192

    const uint32_t dynB = smem_u32(dsm);
    const uint32_t tb   = (dynB + 1023u) & ~1023u;

    if (tid < 256) {
        qs[tid] = g_q[b * H_ + n0 + tid];
        Vs[tid] = Vv[n0 + tid];
    }

    // cp.async slots: A: ra = tid>>2, qa = tid&3 (2x cp16)
    //                 B: rb2 = tid>>1, seg = tid&1 (4x cp16)
    const int ra = tid >> 2, qa = tid & 3;
    const int rb2 = tid >> 1, seg = tid & 1;
    const __half* aSrc = g_encF + ((size_t)b * S_ + row0 + ra) * H_ + qa * 16;
    const __half* bSrc = g_w1tF + ((size_t)(n0 + rb2)) * H_ + seg * 32;
    uint32_t offA[2], offB[4];
#pragma unroll
    for (int j = 0; j < 2; ++j)
        offA[j] = SW128((uint32_t)(ra * 128 + qa * 32 + j * 16));
#pragma unroll
    for (int j = 0; j < 4; ++j)
        offB[j] = SW128((uint32_t)(rb2 * 128 + seg * 64 + j * 16));

    // ldmatrix swizzled bases; kq*32 folds with XOR (bits 5..6), stage adds.
    const int rbl = (((lane & 15) >> 3) << 3) + (lane & 7);
    const int c16 = (lane >> 4) << 4;
    const uint32_t aA0 = tb + SW128((uint32_t)((mbase + rbl) * 128 + c16));
    const uint32_t aA1 = tb + SW128((uint32_t)((mbase + 16 + rbl) * 128 + c16));
    const uint32_t aB0 = tb + OFF_B + SW128((uint32_t)((nbase + rbl) * 128 + c16));
    const uint32_t aB1 = tb + OFF_B + SW128((uint32_t)((nbase + 16 + rbl) * 128 + c16));
    const uint32_t aB2 = tb + OFF_B + SW128((uint32_t)((nbase + 32 + rbl) * 128 + c16));
    const uint32_t aB3 = tb + OFF_B + SW128((uint32_t)((nbase + 48 + rbl) * 128 + c16));

    float acc[2][8][4];
#pragma unroll
    for (int i = 0; i < 2; ++i)
#pragma unroll
        for (int j = 0; j < 8; ++j)
#pragma unroll
            for (int q = 0; q < 4; ++q) acc[i][j][q] = 0.f;

    // prologue: stages 0,1,2
#pragma unroll
    for (int s = 0; s < 3; ++s) {
        const uint32_t sb = tb + s * STG;
        cp16(sb + offA[0], aSrc + s * 64);
        cp16(sb + offA[1], aSrc + s * 64 + 8);
#pragma unroll
        for (int j = 0; j < 4; ++j)
            cp16(sb + OFF_B + offB[j], bSrc + s * 64 + j * 8);
        cp_commit();
    }

#pragma unroll
    for (int kc = 0; kc < 8; ++kc) {
        if (kc <= 5) cp_wait2();
        else if (kc == 6) cp_wait1();
        else cp_wait0();
        __syncthreads();

        if (kc < 5) {
            const int ns = kc + 3;
            const uint32_t sb = tb + (ns & 3) * STG;
            cp16(sb + offA[0], aSrc + ns * 64);
            cp16(sb + offA[1], aSrc + ns * 64 + 8);
#pragma unroll
            for (int j = 0; j < 4; ++j)
                cp16(sb + OFF_B + offB[j], bSrc + ns * 64 + j * 8);
            cp_commit();
        }

        const uint32_t so = (kc & 3) * STG;
#pragma unroll
        for (int kq = 0; kq < 4; ++kq) {
            const uint32_t kk = (uint32_t)(kq << 5);
            uint32_t a0[4], a1[4], bf[4][4];
            ldmx4(a0, (aA0 + so) ^ kk);
            ldmx4(a1, (aA1 + so) ^ kk);
            ldmx4(bf[0], (aB0 + so) ^ kk);
            ldmx4(bf[1], (aB1 + so) ^ kk);
            ldmx4(bf[2], (aB2 + so) ^ kk);
            ldmx4(bf[3], (aB3 + so) ^ kk);
#pragma unroll
            for (int t = 0; t < 4; ++t) {
                mma16816(acc[0][t * 2],     a0, bf[t][0], bf[t][2]);
                mma16816(acc[0][t * 2 + 1], a0, bf[t][1], bf[t][3]);
                mma16816(acc[1][t * 2],     a1, bf[t][0], bf[t][2]);
                mma16816(acc[1][t * 2 + 1], a1, bf[t][1], bf[t][3]);
            }
        }
    }
    __syncthreads();

    // ---- epilogue: per-(ngroup,row) race-free slots, then combine ----
    const int gid = lane >> 2, t4 = lane & 3;
#pragma unroll
    for (int mt = 0; mt < 2; ++mt) {
        float s0 = 0.f, s1 = 0.f;
#pragma unroll
        for (int nt = 0; nt < 8; ++nt) {
            int c = nbase + nt * 8 + t4 * 2;
            float q0 = qs[c], q1 = qs[c + 1], v0 = Vs[c], v1 = Vs[c + 1];
            float* d = acc[mt][nt];
            s0 += tanh_fast(d[0] + q0) * v0 + tanh_fast(d[1] + q1) * v1;
            s1 += tanh_fast(d[2] + q0) * v0 + tanh_fast(d[3] + q1) * v1;
        }
        s0 += __shfl_xor_sync(0xffffffffu, s0, 1);
        s0 += __shfl_xor_sync(0xffffffffu, s0, 2);
        s1 += __shfl_xor_sync(0xffffffffu, s1, 1);
        s1 += __shfl_xor_sync(0xffffffffu, s1, 2);
        if (t4 == 0) {
            es4[nidx][mbase + mt * 16 + gid]     = s0;
            es4[nidx][mbase + mt * 16 + gid + 8] = s1;
        }
    }
    __syncthreads();
    if (tid < 128)
        g_ep[nc][b * S_ + row0 + tid] =
            es4[0][tid] + es4[1][tid] + es4[2][tid] + es4[3][tid];
}

// ---------------- K2: single-pass softmax (no max needed: |e| <= sum|V| < 87) --
__global__ __launch_bounds__(256) void stats_kernel(const int* __restrict__ lens,
                                                    float* __restrict__ out) {
    int b = blockIdx.x;
    int tid = threadIdx.x;
    int len = lens[b];
    __shared__ float red[256];

    out[b * H_ + tid] = 0.f;
    out[b * H_ + tid + 256] = 0.f;

    float sm = 0.f;
    for (int s = tid; s < S_; s += 256) {
        int i = b * S_ + s;
        float w = (s < len) ? __expf(g_ep[0][i] + g_ep[1][i]) : 0.f;
        g_energy[i] = w;
        sm += w;
    }
    red[tid] = sm;
    __syncthreads();
    for (int o = 128; o > 0; o >>= 1) {
        if (tid < o) red[tid] += red[tid + o];
        __syncthreads();
    }
    if (tid == 0) g_invden[b] = 1.0f / red[0];
}

// ---------------- K3: context = sum_s w[s] * enc_fp16[b,s,:] ----------------
__global__ __launch_bounds__(256) void context_kernel(const int* __restrict__ lens,
                                                      float* __restrict__ out) {
    const int b     = blockIdx.x >> 5;
    const int chunk = blockIdx.x & 31;
    const int row0  = chunk * 64;
    const int len   = lens[b];
    if (row0 >= len) return;

    __shared__ float ws[64];
    __shared__ float sc[512];
    const int tid = threadIdx.x;
    sc[tid] = 0.f;
    sc[tid + 256] = 0.f;
    if (tid < 64)
        ws[tid] = g_energy[b * S_ + row0 + tid] * g_invden[b];
    __syncthreads();

    const int smax = min(64, len - row0);
    const int cg = tid & 31;   // 16-half column group
    const int rg = tid >> 5;   // row group 0..7
    float acc[16];
#pragma unroll
    for (int i = 0; i < 16; ++i) acc[i] = 0.f;

    const char* basep = (const char*)(g_encF + ((size_t)b * S_ + row0) * H_) + cg * 32;
#pragma unroll 4
    for (int s = rg; s < smax; s += 8) {
        const uint4* p = (const uint4*)(basep + (size_t)s * 1024);
        uint4 v0 = p[0], v1 = p[1];
        float w = ws[s];
        const uint32_t* u0 = (const uint32_t*)&v0;
        const uint32_t* u1 = (const uint32_t*)&v1;
#pragma unroll
        for (int j = 0; j < 4; ++j) {
            float2 f0 = __half22float2(*(const __half2*)&u0[j]);
            float2 f1 = __half22float2(*(const __half2*)&u1[j]);
            acc[j * 2]     += w * f0.x;
            acc[j * 2 + 1] += w * f0.y;
            acc[8 + j * 2]     += w * f1.x;
            acc[8 + j * 2 + 1] += w * f1.y;
        }
    }
#pragma unroll
    for (int i = 0; i < 16; ++i)
        atomicAdd(&sc[cg * 16 + ((i < 8) ? i : (8 + (i - 8)))], acc[i]);
    __syncthreads();
    atomicAdd(&out[b * H_ + tid], sc[tid]);
    atomicAdd(&out[b * H_ + tid + 256], sc[tid + 256]);
}

// ---------------- launch ----------------
extern "C" void kernel_launch(void* const* d_in, const int* in_sizes, int n_in,
                              void* d_out, int out_size) {
    const float* dec  = (const float*)d_in[0];
    const float* enc  = (const float*)d_in[1];
    const int*   lens = (const int*)d_in[2];
    const float* W1   = (const float*)d_in[3];
    const float* W2   = (const float*)d_in[4];
    const float* V    = (const float*)d_in[5];
    float* out = (float*)d_out;

    cudaFuncSetAttribute(energy_kernel,
                         cudaFuncAttributeMaxDynamicSharedMemorySize, DSMEM);

    prep_kernel<<<9280, 256>>>(enc, lens, W1, dec, W2);
    energy_kernel<<<B_ * 32, 512, DSMEM>>>(V, lens);
    stats_kernel<<<B_, 256>>>(lens, out);
    context_kernel<<<B_ * (S_ / 64), 256>>>(lens, out);
}

// round 10
// speedup vs baseline: 1.1425x; 1.1425x over previous
#include <cuda_runtime.h>
#include <cuda_fp16.h>
#include <cstdint>
#include <cstddef>

#define B_ 64
#define S_ 2048
#define H_ 512

// ---------------- scratch (no allocations allowed) ----------------
__device__ float g_q[B_ * H_];            // query projection [B,H]
__device__ float g_ep[2][B_ * S_];        // energy partials per n-half
__device__ float g_energy[B_ * S_];       // exp(energy) weights (0 when masked)
__device__ float g_invden[B_];
__device__ __half g_w1tF[H_ * H_];        // W1^T fp16 [n][k]
__device__ __half g_encF[(size_t)B_ * S_ * H_];  // enc fp16

// ---------------- helpers ----------------
__device__ __forceinline__ uint32_t smem_u32(const void* p) {
    uint32_t a;
    asm("{ .reg .u64 t; cvta.to.shared.u64 t, %1; cvt.u32.u64 %0, t; }" : "=r"(a) : "l"(p));
    return a;
}
#define SW128(o) ((o) ^ (((o) >> 3) & 0x70))

__device__ __forceinline__ uint32_t cvtf2(float lo, float hi) {  // f16x2 {hi,lo}
    uint32_t r;
    asm("cvt.rn.f16x2.f32 %0, %1, %2;" : "=r"(r) : "f"(hi), "f"(lo));
    return r;
}
__device__ __forceinline__ float tanh_fast(float x) {
    float e = __expf(2.0f * x);
    return 1.0f - __fdividef(2.0f, e + 1.0f);
}
__device__ __forceinline__ void cp16(uint32_t dst, const void* src) {
    asm volatile("cp.async.cg.shared.global [%0], [%1], 16;" :: "r"(dst), "l"(src) : "memory");
}
__device__ __forceinline__ void cp_commit() {
    asm volatile("cp.async.commit_group;" ::: "memory");
}
__device__ __forceinline__ void cp_wait2() {
    asm volatile("cp.async.wait_group 2;" ::: "memory");
}
__device__ __forceinline__ void cp_wait1() {
    asm volatile("cp.async.wait_group 1;" ::: "memory");
}
__device__ __forceinline__ void cp_wait0() {
    asm volatile("cp.async.wait_group 0;" ::: "memory");
}
__device__ __forceinline__ void ldmx4(uint32_t* r, uint32_t addr) {
    asm volatile("ldmatrix.sync.aligned.m8n8.x4.shared.b16 {%0,%1,%2,%3}, [%4];"
                 : "=r"(r[0]), "=r"(r[1]), "=r"(r[2]), "=r"(r[3]) : "r"(addr));
}
__device__ __forceinline__ void mma16816(float* d, const uint32_t* a, uint32_t b0, uint32_t b1) {
    asm volatile(
        "mma.sync.aligned.m16n8k16.row.col.f32.f16.f16.f32 "
        "{%0,%1,%2,%3}, {%4,%5,%6,%7}, {%8,%9}, {%0,%1,%2,%3};"
        : "+f"(d[0]), "+f"(d[1]), "+f"(d[2]), "+f"(d[3])
        : "r"(a[0]), "r"(a[1]), "r"(a[2]), "r"(a[3]), "r"(b0), "r"(b1));
}

// ---------------- K0: fused prep (encconv | w1conv | qproj) ----------------
__global__ __launch_bounds__(256) void prep_kernel(const float* __restrict__ enc,
                                                   const int* __restrict__ lens,
                                                   const float* __restrict__ W1,
                                                   const float* __restrict__ dec,
                                                   const float* __restrict__ W2) {
    const int blk = blockIdx.x;
    const int tid = threadIdx.x;

    if (blk < 8192) {                       // ---- encconv (16 rows each) ----
        const int b    = blk >> 7;
        const int row0 = (blk & 127) << 4;
        const int lim  = ((lens[b] + 127) >> 7) << 7;
        if (row0 >= lim) return;
        const size_t base = ((size_t)b * S_ + row0) * H_;
        const float4* src = (const float4*)(enc + base);
        uint2* dh = (uint2*)(g_encF + base);
#pragma unroll 4
        for (int i = tid; i < 2048; i += 256) {
            float4 v = src[i];
            dh[i] = make_uint2(cvtf2(v.x, v.y), cvtf2(v.z, v.w));
        }
    } else if (blk < 9216) {                // ---- w1conv ----
        int idx = (blk - 8192) * 256 + tid; // idx = n*512 + k
        int n = idx >> 9, k = idx & 511;
        g_w1tF[idx] = __float2half(W1[(size_t)k * H_ + n]);
    } else {                                // ---- qproj ----
        const int b = blk - 9216;
        __shared__ float xs[H_];
        xs[tid] = dec[b * H_ + tid];
        xs[tid + 256] = dec[b * H_ + tid + 256];
        __syncthreads();
        float a0 = 0.f, a1 = 0.f;
#pragma unroll 8
        for (int h = 0; h < H_; ++h) {
            float x = xs[h];
            a0 += x * W2[(size_t)h * H_ + tid];
            a1 += x * W2[(size_t)h * H_ + tid + 256];
        }
        g_q[b * H_ + tid] = a0;
        g_q[b * H_ + tid + 256] = a1;
    }
}

// ---------------- K1: fp16 mma.sync energy GEMM ----------------
// CTA: 128 rows x 256 cols, K=512 in 8 chunks of 64, 4-stage cp.async pipeline.
// 16 warps, warp grid 4M x 4N, warp tile 32x64. 1 CTA/SM (193KB smem).
#define STG    49152       // per-stage: A 16KB + B 32KB
#define OFF_B  16384
#define DSMEM  (1024 + 4 * STG)   // 197632

__global__ __launch_bounds__(512, 1) void energy_kernel(const float* __restrict__ Vv,
                                                        const int* __restrict__ lens) {
    // grid: b*32 + tile*2 + nc
    const int nc   = blockIdx.x & 1;
    const int tile = (blockIdx.x >> 1) & 15;
    const int b    = blockIdx.x >> 5;
    const int row0 = tile << 7;
    const int n0   = nc << 8;
    if (row0 >= lens[b]) return;

    extern __shared__ char dsm[];
    __shared__ float qs[256], Vs[256], es4[4][128];

    const int tid  = threadIdx.x;
    const int wid  = tid >> 5;
    const int lane = tid & 31;
    const int mbase = (wid & 3) << 5;   // 0..96
    const int nidx  = wid >> 2;         // 0..3
    const int nbase = nidx << 6;        // 0..192

    const uint32_t dynB = smem_u32(dsm);
    const uint32_t tb   = (dynB + 1023u) & ~1023u;

    if (tid < 256) {
        qs[tid] = g_q[b * H_ + n0 + tid];
        Vs[tid] = Vv[n0 + tid];
    }

    // cp.async slots: A: ra = tid>>2, qa = tid&3 (2x cp16)
    //                 B: rb2 = tid>>1, seg = tid&1 (4x cp16)
    const int ra = tid >> 2, qa = tid & 3;
    const int rb2 = tid >> 1, seg = tid & 1;
    const __half* aSrc = g_encF + ((size_t)b * S_ + row0 + ra) * H_ + qa * 16;
    const __half* bSrc = g_w1tF + ((size_t)(n0 + rb2)) * H_ + seg * 32;
    uint32_t offA[2], offB[4];
#pragma unroll
    for (int j = 0; j < 2; ++j)
        offA[j] = SW128((uint32_t)(ra * 128 + qa * 32 + j * 16));
#pragma unroll
    for (int j = 0; j < 4; ++j)
        offB[j] = SW128((uint32_t)(rb2 * 128 + seg * 64 + j * 16));

    // ldmatrix swizzled bases; kq*32 folds with XOR (bits 5..6), stage adds.
    const int rbl = (((lane & 15) >> 3) << 3) + (lane & 7);
    const int c16 = (lane >> 4) << 4;
    const uint32_t aA0 = tb + SW128((uint32_t)((mbase + rbl) * 128 + c16));
    const uint32_t aA1 = tb + SW128((uint32_t)((mbase + 16 + rbl) * 128 + c16));
    const uint32_t aB0 = tb + OFF_B + SW128((uint32_t)((nbase + rbl) * 128 + c16));
    const uint32_t aB1 = tb + OFF_B + SW128((uint32_t)((nbase + 16 + rbl) * 128 + c16));
    const uint32_t aB2 = tb + OFF_B + SW128((uint32_t)((nbase + 32 + rbl) * 128 + c16));
    const uint32_t aB3 = tb + OFF_B + SW128((uint32_t)((nbase + 48 + rbl) * 128 + c16));

    float acc[2][8][4];
#pragma unroll
    for (int i = 0; i < 2; ++i)
#pragma unroll
        for (int j = 0; j < 8; ++j)
#pragma unroll
            for (int q = 0; q < 4; ++q) acc[i][j][q] = 0.f;

    // prologue: stages 0,1,2
#pragma unroll
    for (int s = 0; s < 3; ++s) {
        const uint32_t sb = tb + s * STG;
        cp16(sb + offA[0], aSrc + s * 64);
        cp16(sb + offA[1], aSrc + s * 64 + 8);
#pragma unroll
        for (int j = 0; j < 4; ++j)
            cp16(sb + OFF_B + offB[j], bSrc + s * 64 + j * 8);
        cp_commit();
    }

#pragma unroll
    for (int kc = 0; kc < 8; ++kc) {
        if (kc <= 5) cp_wait2();
        else if (kc == 6) cp_wait1();
        else cp_wait0();
        __syncthreads();

        if (kc < 5) {
            const int ns = kc + 3;
            const uint32_t sb = tb + (ns & 3) * STG;
            cp16(sb + offA[0], aSrc + ns * 64);
            cp16(sb + offA[1], aSrc + ns * 64 + 8);
#pragma unroll
            for (int j = 0; j < 4; ++j)
                cp16(sb + OFF_B + offB[j], bSrc + ns * 64 + j * 8);
            cp_commit();
        }

        const uint32_t so = (kc & 3) * STG;
#pragma unroll
        for (int kq = 0; kq < 4; ++kq) {
            const uint32_t kk = (uint32_t)(kq << 5);
            uint32_t a0[4], a1[4], bf[4][4];
            ldmx4(a0, (aA0 + so) ^ kk);
            ldmx4(a1, (aA1 + so) ^ kk);
            ldmx4(bf[0], (aB0 + so) ^ kk);
            ldmx4(bf[1], (aB1 + so) ^ kk);
            ldmx4(bf[2], (aB2 + so) ^ kk);
            ldmx4(bf[3], (aB3 + so) ^ kk);
#pragma unroll
            for (int t = 0; t < 4; ++t) {
                mma16816(acc[0][t * 2],     a0, bf[t][0], bf[t][2]);
                mma16816(acc[0][t * 2 + 1], a0, bf[t][1], bf[t][3]);
                mma16816(acc[1][t * 2],     a1, bf[t][0], bf[t][2]);
                mma16816(acc[1][t * 2 + 1], a1, bf[t][1], bf[t][3]);
            }
        }
    }
    __syncthreads();

    // ---- epilogue: per-(ngroup,row) race-free slots, then combine ----
    const int gid = lane >> 2, t4 = lane & 3;
#pragma unroll
    for (int mt = 0; mt < 2; ++mt) {
        float s0 = 0.f, s1 = 0.f;
#pragma unroll
        for (int nt = 0; nt < 8; ++nt) {
            int c = nbase + nt * 8 + t4 * 2;
            float q0 = qs[c], q1 = qs[c + 1], v0 = Vs[c], v1 = Vs[c + 1];
            float* d = acc[mt][nt];
            s0 += tanh_fast(d[0] + q0) * v0 + tanh_fast(d[1] + q1) * v1;
            s1 += tanh_fast(d[2] + q0) * v0 + tanh_fast(d[3] + q1) * v1;
        }
        s0 += __shfl_xor_sync(0xffffffffu, s0, 1);
        s0 += __shfl_xor_sync(0xffffffffu, s0, 2);
        s1 += __shfl_xor_sync(0xffffffffu, s1, 1);
        s1 += __shfl_xor_sync(0xffffffffu, s1, 2);
        if (t4 == 0) {
            es4[nidx][mbase + mt * 16 + gid]     = s0;
            es4[nidx][mbase + mt * 16 + gid + 8] = s1;
        }
    }
    __syncthreads();
    if (tid < 128)
        g_ep[nc][b * S_ + row0 + tid] =
            es4[0][tid] + es4[1][tid] + es4[2][tid] + es4[3][tid];
}

// ---------------- K2: single-pass softmax (no max needed: |e| <= sum|V| < 87) --
__global__ __launch_bounds__(256) void stats_kernel(const int* __restrict__ lens,
                                                    float* __restrict__ out) {
    int b = blockIdx.x;
    int tid = threadIdx.x;
    int len = lens[b];
    __shared__ float red[256];

    out[b * H_ + tid] = 0.f;
    out[b * H_ + tid + 256] = 0.f;

    float sm = 0.f;
    for (int s = tid; s < S_; s += 256) {
        int i = b * S_ + s;
        float w = (s < len) ? __expf(g_ep[0][i] + g_ep[1][i]) : 0.f;
        g_energy[i] = w;
        sm += w;
    }
    red[tid] = sm;
    __syncthreads();
    for (int o = 128; o > 0; o >>= 1) {
        if (tid < o) red[tid] += red[tid + o];
        __syncthreads();
    }
    if (tid == 0) g_invden[b] = 1.0f / red[0];
}

// ---------------- K3: context = sum_s w[s] * enc_fp16[b,s,:] ----------------
// (round-8 structure: per-thread half2, coalesced across threads; 18us @ 50% DRAM)
__global__ __launch_bounds__(256) void context_kernel(const int* __restrict__ lens,
                                                      float* __restrict__ out) {
    const int b     = blockIdx.x >> 5;
    const int chunk = blockIdx.x & 31;
    const int row0  = chunk * 64;
    const int len   = lens[b];
    if (row0 >= len) return;

    __shared__ float ws[64];
    const int tid = threadIdx.x;
    if (tid < 64)
        ws[tid] = g_energy[b * S_ + row0 + tid] * g_invden[b];
    __syncthreads();

    const int smax = min(64, len - row0);
    const __half2* base = (const __half2*)(g_encF + ((size_t)b * S_ + row0) * H_) + tid;
    float c0 = 0.f, c1 = 0.f;
#pragma unroll 8
    for (int s = 0; s < smax; ++s) {
        float2 f = __half22float2(base[s * 256]);
        float w = ws[s];
        c0 += w * f.x;
        c1 += w * f.y;
    }
    atomicAdd(&out[b * H_ + tid * 2], c0);
    atomicAdd(&out[b * H_ + tid * 2 + 1], c1);
}

// ---------------- launch ----------------
extern "C" void kernel_launch(void* const* d_in, const int* in_sizes, int n_in,
                              void* d_out, int out_size) {
    const float* dec  = (const float*)d_in[0];
    const float* enc  = (const float*)d_in[1];
    const int*   lens = (const int*)d_in[2];
    const float* W1   = (const float*)d_in[3];
    const float* W2   = (const float*)d_in[4];
    const float* V    = (const float*)d_in[5];
    float* out = (float*)d_out;

    cudaFuncSetAttribute(energy_kernel,
                         cudaFuncAttributeMaxDynamicSharedMemorySize, DSMEM);

    prep_kernel<<<9280, 256>>>(enc, lens, W1, dec, W2);
    energy_kernel<<<B_ * 32, 512, DSMEM>>>(V, lens);
    stats_kernel<<<B_, 256>>>(lens, out);
    context_kernel<<<B_ * (S_ / 64), 256>>>(lens, out);
}